// round 5
// baseline (speedup 1.0000x reference)
#include <cuda_runtime.h>

#define HH 256
#define WW 256
#define PP (HH * WW)
#define NF 13776
#define NV 6890
#define BATCH 2
#define BIGF 1000000000.0f
#define EPSF 1e-8f
#define TILE 16
#define TGRID 16
#define NTILES (TGRID * TGRID)
#define NSLICE 8
#define TPB 128

__device__ float4 g_fa[BATCH * NF];       // A0*inv, B0*inv, A1*inv, B1*inv
__device__ float4 g_fb[BATCH * NF];       // -x2, -y2, z0, z1
__device__ float2 g_fc[BATCH * NF];       // z2, face_index (int bits)
__device__ float4 g_bb[BATCH * NF];       // xmin, xmax, ymin, ymax
__device__ float2 g_sf[BATCH * NF * 3];   // src flow per corner
__device__ unsigned long long g_zb[BATCH * PP];
__device__ int g_list[(size_t)BATCH * NTILES * NF];  // per-tile face lists (unordered)
__device__ int g_cnt[BATCH * NTILES];

#define MUL_F32X2(out, a, b) asm("mul.rn.f32x2 %0, %1, %2;" : "=l"(out) : "l"(a), "l"(b))
#define ADD_F32X2(out, a, b) asm("add.rn.f32x2 %0, %1, %2;" : "=l"(out) : "l"(a), "l"(b))
#define FMA_F32X2(out, a, b, c) asm("fma.rn.f32x2 %0, %1, %2, %3;" : "=l"(out) : "l"(a), "l"(b), "l"(c))

__device__ __forceinline__ unsigned int f2sortable(float d) {
    unsigned int u = __float_as_uint(d);
    return u ^ (((unsigned int)((int)u >> 31)) | 0x80000000u);
}

__global__ void setup_kernel(const float* __restrict__ src_cam,
                             const float* __restrict__ src_verts,
                             const float* __restrict__ tgt_cam,
                             const float* __restrict__ tgt_verts,
                             const int*   __restrict__ faces)
{
    int idx = blockIdx.x * blockDim.x + threadIdx.x;
    if (idx >= BATCH * NF) return;
    int b = idx / NF;
    int f = idx - b * NF;

    int i0 = faces[f * 3 + 0];
    int i1 = faces[f * 3 + 1];
    int i2 = faces[f * 3 + 2];

    float tc0 = tgt_cam[b * 3 + 0];
    float tc1 = tgt_cam[b * 3 + 1];
    float tc2 = tgt_cam[b * 3 + 2];
    const float* tv = tgt_verts + (size_t)b * NV * 3;

    float x0 = tc0 * (tv[i0 * 3 + 0] + tc1);
    float y0 = -(tc0 * (tv[i0 * 3 + 1] + tc2));
    float z0 = tv[i0 * 3 + 2];
    float x1 = tc0 * (tv[i1 * 3 + 0] + tc1);
    float y1 = -(tc0 * (tv[i1 * 3 + 1] + tc2));
    float z1 = tv[i1 * 3 + 2];
    float x2 = tc0 * (tv[i2 * 3 + 0] + tc1);
    float y2 = -(tc0 * (tv[i2 * 3 + 1] + tc2));
    float z2 = tv[i2 * 3 + 2];

    float denom = (y1 - y2) * (x0 - x2) + (x2 - x1) * (y0 - y2);
    bool valid = fabsf(denom) >= EPSF;
    float inv = 1.0f / (valid ? denom : 1.0f);

    g_fa[idx] = make_float4((y1 - y2) * inv, (x2 - x1) * inv,
                            (y2 - y0) * inv, (x0 - x2) * inv);
    g_fb[idx] = make_float4(-x2, -y2, z0, z1);
    g_fc[idx] = make_float2(z2, __int_as_float(f));

    const float pad = 2.0f / 256.0f;
    float xmn = fminf(x0, fminf(x1, x2)) - pad;
    float xmx = fmaxf(x0, fmaxf(x1, x2)) + pad;
    float ymn = fminf(y0, fminf(y1, y2)) - pad;
    float ymx = fmaxf(y0, fmaxf(y1, y2)) + pad;
    if (!valid) { xmn = 1e30f; xmx = -1e30f; ymn = 1e30f; ymx = -1e30f; }
    g_bb[idx] = make_float4(xmn, xmx, ymn, ymx);

    float sc0 = src_cam[b * 3 + 0];
    float sc1 = src_cam[b * 3 + 1];
    float sc2 = src_cam[b * 3 + 2];
    const float* sv = src_verts + (size_t)b * NV * 3;
    g_sf[idx * 3 + 0] = make_float2(sc0 * (sv[i0 * 3 + 0] + sc1), sc0 * (sv[i0 * 3 + 1] + sc2));
    g_sf[idx * 3 + 1] = make_float2(sc0 * (sv[i1 * 3 + 0] + sc1), sc0 * (sv[i1 * 3 + 1] + sc2));
    g_sf[idx * 3 + 2] = make_float2(sc0 * (sv[i2 * 3 + 0] + sc1), sc0 * (sv[i2 * 3 + 1] + sc2));
}

__global__ void zinit_kernel()
{
    int i = blockIdx.x * blockDim.x + threadIdx.x;
    if (i < BATCH * PP) {
        g_zb[i] = ((unsigned long long)f2sortable(BIGF) << 32) | 0xFFFFFFFFull;
    }
    if (i < BATCH * NTILES) g_cnt[i] = 0;
}

// face-parallel binning: append face to every tile whose pixel-center rect the
// triangle may touch (conservative half-plane test). Append order is
// nondeterministic, but downstream atomicMin on (depth,faceid) keys is
// order-independent, so the final output is deterministic.
__global__ void bin_kernel()
{
    int idx = blockIdx.x * blockDim.x + threadIdx.x;
    if (idx >= BATCH * NF) return;
    int b = idx / NF;
    int f = idx - b * NF;

    float4 bx = g_bb[idx];
    if (bx.x > bx.y) return;                                  // degenerate
    if (bx.x > 1.0f || bx.y < -1.0f || bx.z > 1.0f || bx.w < -1.0f) return;

    // bbox (already 1px padded) -> tile index range
    float pxmin = (bx.x + 1.0f) * 128.0f - 0.5f;
    float pxmax = (bx.y + 1.0f) * 128.0f - 0.5f;
    float pymin = (bx.z + 1.0f) * 128.0f - 0.5f;
    float pymax = (bx.w + 1.0f) * 128.0f - 0.5f;
    int tx0 = min(max((int)floorf(pxmin * (1.0f / TILE)), 0), TGRID - 1);
    int tx1 = min(max((int)floorf(pxmax * (1.0f / TILE)), 0), TGRID - 1);
    int ty0 = min(max((int)floorf(pymin * (1.0f / TILE)), 0), TGRID - 1);
    int ty1 = min(max((int)floorf(pymax * (1.0f / TILE)), 0), TGRID - 1);

    float4 a  = g_fa[idx];
    float4 c4 = g_fb[idx];   // -x2, -y2
    const float hx = 7.5f / 128.0f;      // half-extent of tile pixel-center rect
    const float hy = 7.5f / 128.0f;
    float sh0 = fabsf(a.x) * hx + fabsf(a.y) * hy;
    float sh1 = fabsf(a.z) * hx + fabsf(a.w) * hy;
    float sh2 = fabsf(a.x + a.z) * hx + fabsf(a.y + a.w) * hy;

    for (int ty = ty0; ty <= ty1; ty++) {
        float cy = ((float)(TILE * ty) + 7.5f + 0.5f) / 128.0f - 1.0f;  // rect center y
        float dyc = cy + c4.y;
        for (int tx = tx0; tx <= tx1; tx++) {
            float cx = ((float)(TILE * tx) + 7.5f + 0.5f) / 128.0f - 1.0f;
            float dxc = cx + c4.x;
            float w0c = a.x * dxc + a.y * dyc;
            float w1c = a.z * dxc + a.w * dyc;
            float w2c = 1.0f - w0c - w1c;
            float m0 = 1e-5f * (fabsf(w0c) + sh0) + 1e-6f;
            float m1 = 1e-5f * (fabsf(w1c) + sh1) + 1e-6f;
            float m2 = 1e-5f * (fabsf(w2c) + sh2) + 1e-6f;
            if ((w0c + sh0 >= -m0) & (w1c + sh1 >= -m1) & (w2c + sh2 >= -m2)) {
                int t = b * NTILES + ty * TGRID + tx;
                int pos = atomicAdd(&g_cnt[t], 1);
                g_list[(size_t)t * NF + pos] = f;
            }
        }
    }
}

__global__ __launch_bounds__(TPB) void raster_kernel()
{
    __shared__ float4 sA[TPB];  // (ax,ax,ay,ay)
    __shared__ float4 sB[TPB];  // (az,az,aw,aw)
    __shared__ float4 sC[TPB];  // (nx2,nx2,ny2,ny2)
    __shared__ float4 sD[TPB];  // (z0,z0,z1,z1)
    __shared__ float4 sE[TPB];  // (z2,z2,fid,fid)

    const int b     = blockIdx.z;
    const int slice = blockIdx.y;
    const int tile  = blockIdx.x;
    const int tx    = tile & (TGRID - 1);
    const int ty    = tile >> 4;
    const int tid   = threadIdx.x;

    const int len   = g_cnt[b * NTILES + tile];
    const int start = (len * slice) / NSLICE;
    const int end   = (len * (slice + 1)) / NSLICE;
    if (start >= end) return;

    const int* lst = g_list + (size_t)(b * NTILES + tile) * NF;
    const float4* __restrict__ fa = g_fa + b * NF;
    const float4* __restrict__ fb = g_fb + b * NF;
    const float2* __restrict__ fc = g_fc + b * NF;

    const int p0    = tid * 2;
    const int px0_i = tx * TILE + (p0 & 15);
    const int py_i  = ty * TILE + (p0 >> 4);
    const float px0 = ((float)px0_i + 0.5f) / 256.0f * 2.0f - 1.0f;
    const float px1 = ((float)(px0_i + 1) + 0.5f) / 256.0f * 2.0f - 1.0f;
    const float py  = ((float)py_i + 0.5f) / 256.0f * 2.0f - 1.0f;

    unsigned long long pxp, pyp;
    asm("mov.b64 %0, {%1, %2};" : "=l"(pxp) : "r"(__float_as_uint(px0)), "r"(__float_as_uint(px1)));
    asm("mov.b64 %0, {%1, %2};" : "=l"(pyp) : "r"(__float_as_uint(py)),  "r"(__float_as_uint(py)));
    const unsigned long long onesp    = 0x3f8000003f800000ull;
    const unsigned long long negonesp = 0xbf800000bf800000ull;

    float zmin0 = BIGF, zmin1 = BIGF;
    int   best0 = -1,   best1 = -1;

    for (int base = start; base < end; base += TPB) {
        int e = base + tid;
        if (e < end) {
            int f = lst[e];
            float4 a  = fa[f];
            float4 c4 = fb[f];
            float2 e2 = fc[f];
            sA[tid] = make_float4(a.x, a.x, a.y, a.y);
            sB[tid] = make_float4(a.z, a.z, a.w, a.w);
            sC[tid] = make_float4(c4.x, c4.x, c4.y, c4.y);
            sD[tid] = make_float4(c4.z, c4.z, c4.w, c4.w);
            sE[tid] = make_float4(e2.x, e2.x, e2.y, e2.y);
        }
        __syncthreads();
        int cnt2 = min(TPB, end - base);

        const ulonglong2* qA = (const ulonglong2*)sA;
        const ulonglong2* qB = (const ulonglong2*)sB;
        const ulonglong2* qC = (const ulonglong2*)sC;
        const ulonglong2* qD = (const ulonglong2*)sD;
        const ulonglong2* qE = (const ulonglong2*)sE;

        for (int k = 0; k < cnt2; k++) {
            ulonglong2 a01 = qA[k];
            ulonglong2 a23 = qB[k];
            ulonglong2 cxy = qC[k];
            ulonglong2 z01 = qD[k];
            ulonglong2 z2f = qE[k];

            unsigned long long dxp, dyp, t0, t1, w0, w1, tmp, w2, d;
            ADD_F32X2(dxp, pxp, cxy.x);
            ADD_F32X2(dyp, pyp, cxy.y);
            MUL_F32X2(t0, a01.y, dyp);
            FMA_F32X2(w0, a01.x, dxp, t0);
            MUL_F32X2(t1, a23.y, dyp);
            FMA_F32X2(w1, a23.x, dxp, t1);
            FMA_F32X2(tmp, w0, negonesp, onesp);   // 1 - w0
            FMA_F32X2(w2,  w1, negonesp, tmp);     // (1-w0) - w1
            MUL_F32X2(d, w2, z2f.x);
            FMA_F32X2(d, w1, z01.y, d);
            FMA_F32X2(d, w0, z01.x, d);

            unsigned long long orb = w0 | w1 | w2;
            int o_lo = (int)(unsigned)orb;
            int o_hi = (int)(unsigned)(orb >> 32);
            float d0 = __uint_as_float((unsigned)d);
            float d1 = __uint_as_float((unsigned)(d >> 32));
            int fid = (int)(unsigned)z2f.y;

            if ((o_lo >= 0) && (d0 < zmin0)) { zmin0 = d0; best0 = fid; }
            if ((o_hi >= 0) && (d1 < zmin1)) { zmin1 = d1; best1 = fid; }
        }
        __syncthreads();
    }

    unsigned long long* zb = g_zb + (size_t)b * PP;
    if (best0 >= 0) {
        unsigned long long key =
            ((unsigned long long)f2sortable(zmin0) << 32) | (unsigned int)best0;
        atomicMin(&zb[py_i * WW + px0_i], key);
    }
    if (best1 >= 0) {
        unsigned long long key =
            ((unsigned long long)f2sortable(zmin1) << 32) | (unsigned int)best1;
        atomicMin(&zb[py_i * WW + px0_i + 1], key);
    }
}

__global__ __launch_bounds__(256) void resolve_kernel(const float* __restrict__ src_img,
                                                      float* __restrict__ out)
{
    const int b   = blockIdx.y;
    const int pix = blockIdx.x * 256 + threadIdx.x;
    const int px_i = pix & (WW - 1);
    const int py_i = pix >> 8;
    const float px = ((float)px_i + 0.5f) / 256.0f * 2.0f - 1.0f;
    const float py = ((float)py_i + 0.5f) / 256.0f * 2.0f - 1.0f;

    unsigned long long key = g_zb[(size_t)b * PP + pix];
    unsigned int face = (unsigned int)(key & 0xFFFFFFFFull);

    float fx, fy;
    if (face != 0xFFFFFFFFu) {
        int gi = b * NF + (int)face;
        float4 a  = g_fa[gi];
        float4 c4 = g_fb[gi];   // -x2, -y2
        float dx = px + c4.x;
        float dy = py + c4.y;
        float w0 = fmaf(a.x, dx, a.y * dy);
        float w1 = fmaf(a.z, dx, a.w * dy);
        float w2 = 1.0f - w0 - w1;
        float2 s0 = g_sf[gi * 3 + 0];
        float2 s1 = g_sf[gi * 3 + 1];
        float2 s2 = g_sf[gi * 3 + 2];
        fx = w0 * s0.x + w1 * s1.x + w2 * s2.x;
        fy = w0 * s0.y + w1 * s1.y + w2 * s2.y;
    } else {
        fx = -2.0f;
        fy = -2.0f;
    }

    float ix = fminf(fmaxf(((fx + 1.0f) * 256.0f - 1.0f) * 0.5f, 0.0f), 255.0f);
    float iy = fminf(fmaxf(((fy + 1.0f) * 256.0f - 1.0f) * 0.5f, 0.0f), 255.0f);
    float x0f = floorf(ix);
    float y0f = floorf(iy);
    float wx = ix - x0f;
    float wy = iy - y0f;
    int x0i = (int)x0f;
    int y0i = (int)y0f;
    int x1i = min(x0i + 1, WW - 1);
    int y1i = min(y0i + 1, HH - 1);

    float wa = (1.0f - wx) * (1.0f - wy);
    float wb = wx * (1.0f - wy);
    float wc = (1.0f - wx) * wy;
    float wd = wx * wy;

    const float* img = src_img + (size_t)b * 3 * HH * WW;
    #pragma unroll
    for (int c = 0; c < 3; c++) {
        const float* p = img + (size_t)c * HH * WW;
        float Ia = p[y0i * WW + x0i];
        float Ib = p[y0i * WW + x1i];
        float Ic = p[y1i * WW + x0i];
        float Id = p[y1i * WW + x1i];
        out[(((size_t)b * 3 + c) * HH + py_i) * WW + px_i] =
            Ia * wa + Ib * wb + Ic * wc + Id * wd;
    }
}

extern "C" void kernel_launch(void* const* d_in, const int* in_sizes, int n_in,
                              void* d_out, int out_size)
{
    const float* src_img   = (const float*)d_in[0];
    const float* src_cam   = (const float*)d_in[1];
    const float* src_verts = (const float*)d_in[2];
    const float* tgt_cam   = (const float*)d_in[3];
    const float* tgt_verts = (const float*)d_in[4];
    const int*   faces     = (const int*)d_in[5];
    float* out = (float*)d_out;

    int n = BATCH * NF;
    setup_kernel<<<(n + 255) / 256, 256>>>(src_cam, src_verts, tgt_cam, tgt_verts, faces);
    zinit_kernel<<<(BATCH * PP + 255) / 256, 256>>>();
    bin_kernel<<<(n + 255) / 256, 256>>>();
    dim3 rgrid(NTILES, NSLICE, BATCH);
    raster_kernel<<<rgrid, TPB>>>();
    dim3 ggrid(PP / 256, BATCH);
    resolve_kernel<<<ggrid, 256>>>(src_img, out);
}

// round 7
// speedup vs baseline: 2.0956x; 2.0956x over previous
#include <cuda_runtime.h>

#define HH 256
#define WW 256
#define PP (HH * WW)
#define NF 13776
#define NV 6890
#define BATCH 2
#define BIGF 1000000000.0f
#define EPSF 1e-8f
#define TILE 16
#define NSEG 16
#define SEGLEN ((NF + NSEG - 1) / NSEG)
#define CULL 128
#define NWARPS 4

// Precomputed per-(batch,face) data (SoA, device scratch — no allocs)
__device__ float4 g_fa[BATCH * NF];       // A0*inv, B0*inv, A1*inv, B1*inv
__device__ float4 g_fb[BATCH * NF];       // x2, y2, z0, z1
__device__ float2 g_fc[BATCH * NF];       // z2, face_index (int bits)
__device__ float4 g_bb[BATCH * NF];       // xmin, xmax, ymin, ymax
__device__ float2 g_sf[BATCH * NF * 3];   // src flow per corner
__device__ unsigned long long g_zb[BATCH * PP];

__device__ __forceinline__ unsigned int f2sortable(float d) {
    unsigned int u = __float_as_uint(d);
    return u ^ (((unsigned int)((int)u >> 31)) | 0x80000000u);
}

__global__ void setup_kernel(const float* __restrict__ src_cam,
                             const float* __restrict__ src_verts,
                             const float* __restrict__ tgt_cam,
                             const float* __restrict__ tgt_verts,
                             const int*   __restrict__ faces)
{
    int idx = blockIdx.x * blockDim.x + threadIdx.x;
    if (idx >= BATCH * NF) return;
    int b = idx / NF;
    int f = idx - b * NF;

    int i0 = faces[f * 3 + 0];
    int i1 = faces[f * 3 + 1];
    int i2 = faces[f * 3 + 2];

    float tc0 = tgt_cam[b * 3 + 0];
    float tc1 = tgt_cam[b * 3 + 1];
    float tc2 = tgt_cam[b * 3 + 2];
    const float* tv = tgt_verts + (size_t)b * NV * 3;

    float x0 = tc0 * (tv[i0 * 3 + 0] + tc1);
    float y0 = -(tc0 * (tv[i0 * 3 + 1] + tc2));
    float z0 = tv[i0 * 3 + 2];
    float x1 = tc0 * (tv[i1 * 3 + 0] + tc1);
    float y1 = -(tc0 * (tv[i1 * 3 + 1] + tc2));
    float z1 = tv[i1 * 3 + 2];
    float x2 = tc0 * (tv[i2 * 3 + 0] + tc1);
    float y2 = -(tc0 * (tv[i2 * 3 + 1] + tc2));
    float z2 = tv[i2 * 3 + 2];

    float denom = (y1 - y2) * (x0 - x2) + (x2 - x1) * (y0 - y2);
    bool valid = fabsf(denom) >= EPSF;
    float inv = 1.0f / (valid ? denom : 1.0f);

    g_fa[idx] = make_float4((y1 - y2) * inv, (x2 - x1) * inv,
                            (y2 - y0) * inv, (x0 - x2) * inv);
    g_fb[idx] = make_float4(x2, y2, z0, z1);
    g_fc[idx] = make_float2(z2, __int_as_float(f));

    const float pad = 2.0f / 256.0f;
    float xmn = fminf(x0, fminf(x1, x2)) - pad;
    float xmx = fmaxf(x0, fmaxf(x1, x2)) + pad;
    float ymn = fminf(y0, fminf(y1, y2)) - pad;
    float ymx = fmaxf(y0, fmaxf(y1, y2)) + pad;
    if (!valid) { xmn = 1e30f; xmx = -1e30f; ymn = 1e30f; ymx = -1e30f; }
    g_bb[idx] = make_float4(xmn, xmx, ymn, ymx);

    float sc0 = src_cam[b * 3 + 0];
    float sc1 = src_cam[b * 3 + 1];
    float sc2 = src_cam[b * 3 + 2];
    const float* sv = src_verts + (size_t)b * NV * 3;
    g_sf[idx * 3 + 0] = make_float2(sc0 * (sv[i0 * 3 + 0] + sc1), sc0 * (sv[i0 * 3 + 1] + sc2));
    g_sf[idx * 3 + 1] = make_float2(sc0 * (sv[i1 * 3 + 0] + sc1), sc0 * (sv[i1 * 3 + 1] + sc2));
    g_sf[idx * 3 + 2] = make_float2(sc0 * (sv[i2 * 3 + 0] + sc1), sc0 * (sv[i2 * 3 + 1] + sc2));
}

__global__ void zinit_kernel()
{
    int i = blockIdx.x * blockDim.x + threadIdx.x;
    if (i >= BATCH * PP) return;
    g_zb[i] = ((unsigned long long)f2sortable(BIGF) << 32) | 0xFFFFFFFFull;
}

__global__ __launch_bounds__(CULL) void raster_kernel()
{
    __shared__ float4 s_fa[CULL];
    __shared__ float4 s_fb[CULL];
    __shared__ float2 s_fc[CULL];
    __shared__ int    s_wcnt[NWARPS];
    __shared__ int    s_idx[NWARPS][CULL];

    const int b     = blockIdx.z;
    const int seg   = blockIdx.y;
    const int tileX = blockIdx.x & 15;
    const int tileY = blockIdx.x >> 4;
    const int tid   = threadIdx.x;
    const int lane  = tid & 31;
    const int warp  = tid >> 5;

    // each warp owns an 8x8 subtile: warp&1 -> x half, warp>>1 -> y half
    const int sbx = (warp & 1) * 8;
    const int sby = (warp >> 1) * 8;
    const int p0  = lane * 2;
    const int px0_i = tileX * TILE + sbx + (p0 & 7);
    const int py_i  = tileY * TILE + sby + (p0 >> 3);
    const float px0 = ((float)px0_i + 0.5f) / 256.0f * 2.0f - 1.0f;
    const float px1 = ((float)(px0_i + 1) + 0.5f) / 256.0f * 2.0f - 1.0f;
    const float py  = ((float)py_i + 0.5f) / 256.0f * 2.0f - 1.0f;

    // tile pixel-center rectangle (16x16)
    const float tx0 = ((float)(tileX * TILE)            + 0.5f) / 256.0f * 2.0f - 1.0f;
    const float tx1 = ((float)(tileX * TILE + TILE - 1) + 0.5f) / 256.0f * 2.0f - 1.0f;
    const float ty0 = ((float)(tileY * TILE)            + 0.5f) / 256.0f * 2.0f - 1.0f;
    const float ty1 = ((float)(tileY * TILE + TILE - 1) + 0.5f) / 256.0f * 2.0f - 1.0f;
    const float cx  = 0.5f * (tx0 + tx1);
    const float cy  = 0.5f * (ty0 + ty1);
    const float hx  = 0.5f * (tx1 - tx0);
    const float hy  = 0.5f * (ty1 - ty0);

    // subtile pixel-center rect (8x8): center and half-extent
    const float scx = ((float)(tileX * TILE + sbx) + 4.0f) / 128.0f - 1.0f;
    const float scy = ((float)(tileY * TILE + sby) + 4.0f) / 128.0f - 1.0f;
    const float shx = 3.5f / 128.0f;
    const float shy = 3.5f / 128.0f;

    const float4* __restrict__ fa = g_fa + b * NF;
    const float4* __restrict__ fb = g_fb + b * NF;
    const float2* __restrict__ fc = g_fc + b * NF;
    const float4* __restrict__ bb = g_bb + b * NF;

    float zmin0 = BIGF, zmin1 = BIGF;
    int   best0 = -1,   best1 = -1;

    const int fbeg = seg * SEGLEN;
    const int fend = min(fbeg + SEGLEN, NF);

    for (int base = fbeg; base < fend; base += CULL) {
        // ---- level 1: tile cull (coalesced, 1 face/thread) ----
        int f = base + tid;
        bool pass = false;
        if (f < fend) {
            float4 bx = bb[f];
            pass = (bx.x <= tx1) & (bx.y >= tx0) & (bx.z <= ty1) & (bx.w >= ty0);
            if (pass) {
                float4 a  = fa[f];
                float dxc = cx - fb[f].x;
                float dyc = cy - fb[f].y;
                float w0c = a.x * dxc + a.y * dyc;
                float w1c = a.z * dxc + a.w * dyc;
                float w2c = 1.0f - w0c - w1c;
                float s0  = fabsf(a.x) * hx + fabsf(a.y) * hy;
                float s1  = fabsf(a.z) * hx + fabsf(a.w) * hy;
                float s2  = fabsf(a.x + a.z) * hx + fabsf(a.y + a.w) * hy;
                float m0  = 1e-5f * (fabsf(w0c) + s0) + 1e-6f;
                float m1  = 1e-5f * (fabsf(w1c) + s1) + 1e-6f;
                float m2  = 1e-5f * (fabsf(w2c) + s2) + 1e-6f;
                pass = (w0c + s0 >= -m0) & (w1c + s1 >= -m1) & (w2c + s2 >= -m2);
            }
        }
        unsigned m = __ballot_sync(0xffffffffu, pass);
        if (lane == 0) s_wcnt[warp] = __popc(m);
        __syncthreads();

        int off = 0;
        int cnt = 0;
        #pragma unroll
        for (int w = 0; w < NWARPS; w++) {
            int c = s_wcnt[w];
            if (w < warp) off += c;
            cnt += c;
        }
        off += __popc(m & ((1u << lane) - 1u));
        if (pass) {
            s_fa[off] = fa[f];
            s_fb[off] = fb[f];
            s_fc[off] = fc[f];
        }
        __syncthreads();

        // ---- level 2: per-warp 8x8 subtile cull -> warp-local list ----
        int scnt = 0;
        for (int j0 = 0; j0 < cnt; j0 += 32) {
            int j = j0 + lane;
            bool sp = false;
            if (j < cnt) {
                float4 a  = s_fa[j];
                float2 xy = make_float2(s_fb[j].x, s_fb[j].y);
                float dxc = scx - xy.x;
                float dyc = scy - xy.y;
                float w0c = a.x * dxc + a.y * dyc;
                float w1c = a.z * dxc + a.w * dyc;
                float w2c = 1.0f - w0c - w1c;
                float s0  = fabsf(a.x) * shx + fabsf(a.y) * shy;
                float s1  = fabsf(a.z) * shx + fabsf(a.w) * shy;
                float s2  = fabsf(a.x + a.z) * shx + fabsf(a.y + a.w) * shy;
                float m0  = 1e-5f * (fabsf(w0c) + s0) + 1e-6f;
                float m1  = 1e-5f * (fabsf(w1c) + s1) + 1e-6f;
                float m2  = 1e-5f * (fabsf(w2c) + s2) + 1e-6f;
                sp = (w0c + s0 >= -m0) & (w1c + s1 >= -m1) & (w2c + s2 >= -m2);
            }
            unsigned sm = __ballot_sync(0xffffffffu, sp);
            if (sp) s_idx[warp][scnt + __popc(sm & ((1u << lane) - 1u))] = j;
            scnt += __popc(sm);
        }

        // ---- sweep: this warp's subtile list only, 2px/lane ----
        for (int k = 0; k < scnt; k++) {
            int idx   = s_idx[warp][k];
            float4 a  = s_fa[idx];
            float4 c4 = s_fb[idx];
            float2 e  = s_fc[idx];
            float dy  = py  - c4.y;
            float dx0 = px0 - c4.x;
            float dx1 = px1 - c4.x;
            float t0  = a.y * dy;
            float t1  = a.w * dy;
            float w0a = fmaf(a.x, dx0, t0);
            float w0b = fmaf(a.x, dx1, t0);
            float w1a = fmaf(a.z, dx0, t1);
            float w1b = fmaf(a.z, dx1, t1);
            float w2a = 1.0f - w0a - w1a;
            float w2b = 1.0f - w0b - w1b;
            float da  = fmaf(w0a, c4.z, fmaf(w1a, c4.w, w2a * e.x));
            float db  = fmaf(w0b, c4.z, fmaf(w1b, c4.w, w2b * e.x));
            int oa = __float_as_int(w0a) | __float_as_int(w1a) | __float_as_int(w2a);
            int ob = __float_as_int(w0b) | __float_as_int(w1b) | __float_as_int(w2b);
            if ((oa >= 0) && (da < zmin0)) { zmin0 = da; best0 = __float_as_int(e.y); }
            if ((ob >= 0) && (db < zmin1)) { zmin1 = db; best1 = __float_as_int(e.y); }
        }
        __syncthreads();
    }

    unsigned long long* zb = g_zb + (size_t)b * PP;
    if (best0 >= 0) {
        unsigned long long key =
            ((unsigned long long)f2sortable(zmin0) << 32) | (unsigned int)best0;
        atomicMin(&zb[py_i * WW + px0_i], key);
    }
    if (best1 >= 0) {
        unsigned long long key =
            ((unsigned long long)f2sortable(zmin1) << 32) | (unsigned int)best1;
        atomicMin(&zb[py_i * WW + px0_i + 1], key);
    }
}

__global__ __launch_bounds__(256) void resolve_kernel(const float* __restrict__ src_img,
                                                      float* __restrict__ out)
{
    const int b   = blockIdx.y;
    const int pix = blockIdx.x * 256 + threadIdx.x;
    const int px_i = pix & (WW - 1);
    const int py_i = pix >> 8;
    const float px = ((float)px_i + 0.5f) / 256.0f * 2.0f - 1.0f;
    const float py = ((float)py_i + 0.5f) / 256.0f * 2.0f - 1.0f;

    unsigned long long key = g_zb[(size_t)b * PP + pix];
    unsigned int face = (unsigned int)(key & 0xFFFFFFFFull);

    float fx, fy;
    if (face != 0xFFFFFFFFu) {
        int gi = b * NF + (int)face;
        float4 a  = g_fa[gi];
        float4 c4 = g_fb[gi];
        float dx = px - c4.x;
        float dy = py - c4.y;
        float w0 = fmaf(a.x, dx, a.y * dy);
        float w1 = fmaf(a.z, dx, a.w * dy);
        float w2 = 1.0f - w0 - w1;
        float2 s0 = g_sf[gi * 3 + 0];
        float2 s1 = g_sf[gi * 3 + 1];
        float2 s2 = g_sf[gi * 3 + 2];
        fx = w0 * s0.x + w1 * s1.x + w2 * s2.x;
        fy = w0 * s0.y + w1 * s1.y + w2 * s2.y;
    } else {
        fx = -2.0f;
        fy = -2.0f;
    }

    float ix = fminf(fmaxf(((fx + 1.0f) * 256.0f - 1.0f) * 0.5f, 0.0f), 255.0f);
    float iy = fminf(fmaxf(((fy + 1.0f) * 256.0f - 1.0f) * 0.5f, 0.0f), 255.0f);
    float x0f = floorf(ix);
    float y0f = floorf(iy);
    float wx = ix - x0f;
    float wy = iy - y0f;
    int x0i = (int)x0f;
    int y0i = (int)y0f;
    int x1i = min(x0i + 1, WW - 1);
    int y1i = min(y0i + 1, HH - 1);

    float wa = (1.0f - wx) * (1.0f - wy);
    float wb = wx * (1.0f - wy);
    float wc = (1.0f - wx) * wy;
    float wd = wx * wy;

    const float* img = src_img + (size_t)b * 3 * HH * WW;
    #pragma unroll
    for (int c = 0; c < 3; c++) {
        const float* p = img + (size_t)c * HH * WW;
        float Ia = p[y0i * WW + x0i];
        float Ib = p[y0i * WW + x1i];
        float Ic = p[y1i * WW + x0i];
        float Id = p[y1i * WW + x1i];
        out[(((size_t)b * 3 + c) * HH + py_i) * WW + px_i] =
            Ia * wa + Ib * wb + Ic * wc + Id * wd;
    }
}

extern "C" void kernel_launch(void* const* d_in, const int* in_sizes, int n_in,
                              void* d_out, int out_size)
{
    const float* src_img   = (const float*)d_in[0];
    const float* src_cam   = (const float*)d_in[1];
    const float* src_verts = (const float*)d_in[2];
    const float* tgt_cam   = (const float*)d_in[3];
    const float* tgt_verts = (const float*)d_in[4];
    const int*   faces     = (const int*)d_in[5];
    float* out = (float*)d_out;

    int n = BATCH * NF;
    setup_kernel<<<(n + 255) / 256, 256>>>(src_cam, src_verts, tgt_cam, tgt_verts, faces);
    zinit_kernel<<<(BATCH * PP + 255) / 256, 256>>>();
    dim3 rgrid(256, NSEG, BATCH);
    raster_kernel<<<rgrid, CULL>>>();
    dim3 ggrid(PP / 256, BATCH);
    resolve_kernel<<<ggrid, 256>>>(src_img, out);
}

// round 8
// speedup vs baseline: 2.6159x; 1.2483x over previous
#include <cuda_runtime.h>

#define HH 256
#define WW 256
#define PP (HH * WW)
#define NF 13776
#define NV 6890
#define BATCH 2
#define BIGF 1000000000.0f
#define EPSF 1e-8f
#define TILE 16
#define NSEG 16
#define SEGLEN ((NF + NSEG - 1) / NSEG)
#define CULL 128
#define NWARPS 4

// Precomputed per-(batch,face) data (SoA, device scratch — no allocs)
__device__ float4 g_fa[BATCH * NF];       // A0*inv, B0*inv, A1*inv, B1*inv
__device__ float4 g_fb[BATCH * NF];       // x2, y2, z0, z1
__device__ float2 g_fc[BATCH * NF];       // z2, face_index (int bits)
__device__ float4 g_bb[BATCH * NF];       // xmin, xmax, ymin, ymax
__device__ float2 g_dd[BATCH * NF];       // depth gradient (beta, gamma)
__device__ float2 g_sf[BATCH * NF * 3];   // src flow per corner
__device__ unsigned long long g_zb[BATCH * PP];

__device__ __forceinline__ unsigned int f2sortable(float d) {
    unsigned int u = __float_as_uint(d);
    return u ^ (((unsigned int)((int)u >> 31)) | 0x80000000u);
}

__global__ void setup_kernel(const float* __restrict__ src_cam,
                             const float* __restrict__ src_verts,
                             const float* __restrict__ tgt_cam,
                             const float* __restrict__ tgt_verts,
                             const int*   __restrict__ faces)
{
    int idx = blockIdx.x * blockDim.x + threadIdx.x;
    if (idx >= BATCH * NF) return;
    int b = idx / NF;
    int f = idx - b * NF;

    int i0 = faces[f * 3 + 0];
    int i1 = faces[f * 3 + 1];
    int i2 = faces[f * 3 + 2];

    float tc0 = tgt_cam[b * 3 + 0];
    float tc1 = tgt_cam[b * 3 + 1];
    float tc2 = tgt_cam[b * 3 + 2];
    const float* tv = tgt_verts + (size_t)b * NV * 3;

    float x0 = tc0 * (tv[i0 * 3 + 0] + tc1);
    float y0 = -(tc0 * (tv[i0 * 3 + 1] + tc2));
    float z0 = tv[i0 * 3 + 2];
    float x1 = tc0 * (tv[i1 * 3 + 0] + tc1);
    float y1 = -(tc0 * (tv[i1 * 3 + 1] + tc2));
    float z1 = tv[i1 * 3 + 2];
    float x2 = tc0 * (tv[i2 * 3 + 0] + tc1);
    float y2 = -(tc0 * (tv[i2 * 3 + 1] + tc2));
    float z2 = tv[i2 * 3 + 2];

    float denom = (y1 - y2) * (x0 - x2) + (x2 - x1) * (y0 - y2);
    bool valid = fabsf(denom) >= EPSF;
    float inv = 1.0f / (valid ? denom : 1.0f);

    float ax = (y1 - y2) * inv, ay = (x2 - x1) * inv;
    float az = (y2 - y0) * inv, aw = (x0 - x2) * inv;
    g_fa[idx] = make_float4(ax, ay, az, aw);
    g_fb[idx] = make_float4(x2, y2, z0, z1);
    g_fc[idx] = make_float2(z2, __int_as_float(f));
    // depth gradient: d(x,y) = w0 z0 + w1 z1 + w2 z2, w affine
    float beta  = ax * z0 + az * z1 - (ax + az) * z2;
    float gamma = ay * z0 + aw * z1 - (ay + aw) * z2;
    g_dd[idx] = make_float2(beta, gamma);

    const float pad = 2.0f / 256.0f;
    float xmn = fminf(x0, fminf(x1, x2)) - pad;
    float xmx = fmaxf(x0, fmaxf(x1, x2)) + pad;
    float ymn = fminf(y0, fminf(y1, y2)) - pad;
    float ymx = fmaxf(y0, fmaxf(y1, y2)) + pad;
    if (!valid) { xmn = 1e30f; xmx = -1e30f; ymn = 1e30f; ymx = -1e30f; }
    g_bb[idx] = make_float4(xmn, xmx, ymn, ymx);

    float sc0 = src_cam[b * 3 + 0];
    float sc1 = src_cam[b * 3 + 1];
    float sc2 = src_cam[b * 3 + 2];
    const float* sv = src_verts + (size_t)b * NV * 3;
    g_sf[idx * 3 + 0] = make_float2(sc0 * (sv[i0 * 3 + 0] + sc1), sc0 * (sv[i0 * 3 + 1] + sc2));
    g_sf[idx * 3 + 1] = make_float2(sc0 * (sv[i1 * 3 + 0] + sc1), sc0 * (sv[i1 * 3 + 1] + sc2));
    g_sf[idx * 3 + 2] = make_float2(sc0 * (sv[i2 * 3 + 0] + sc1), sc0 * (sv[i2 * 3 + 1] + sc2));
}

__global__ void zinit_kernel()
{
    int i = blockIdx.x * blockDim.x + threadIdx.x;
    if (i >= BATCH * PP) return;
    g_zb[i] = ((unsigned long long)f2sortable(BIGF) << 32) | 0xFFFFFFFFull;
}

__global__ __launch_bounds__(CULL) void raster_kernel()
{
    __shared__ float4 s_fa[CULL];
    __shared__ float4 s_fb[CULL];
    __shared__ float2 s_fc[CULL];
    __shared__ float4 s_dd[CULL];          // (dc_tile, beta, gamma, unused)
    __shared__ int    s_wcnt[NWARPS];
    __shared__ float2 s_sub[NWARPS][CULL]; // (dmin_subtile, idx as int bits)

    const int b     = blockIdx.z;
    const int seg   = blockIdx.y;
    const int tileX = blockIdx.x & 15;
    const int tileY = blockIdx.x >> 4;
    const int tid   = threadIdx.x;
    const int lane  = tid & 31;
    const int warp  = tid >> 5;

    // each warp owns an 8x8 subtile
    const int sbx = (warp & 1) * 8;
    const int sby = (warp >> 1) * 8;
    const int p0  = lane * 2;
    const int px0_i = tileX * TILE + sbx + (p0 & 7);
    const int py_i  = tileY * TILE + sby + (p0 >> 3);
    const float px0 = ((float)px0_i + 0.5f) / 256.0f * 2.0f - 1.0f;
    const float px1 = ((float)(px0_i + 1) + 0.5f) / 256.0f * 2.0f - 1.0f;
    const float py  = ((float)py_i + 0.5f) / 256.0f * 2.0f - 1.0f;

    // tile pixel-center rectangle (16x16)
    const float tx0 = ((float)(tileX * TILE)            + 0.5f) / 256.0f * 2.0f - 1.0f;
    const float tx1 = ((float)(tileX * TILE + TILE - 1) + 0.5f) / 256.0f * 2.0f - 1.0f;
    const float ty0 = ((float)(tileY * TILE)            + 0.5f) / 256.0f * 2.0f - 1.0f;
    const float ty1 = ((float)(tileY * TILE + TILE - 1) + 0.5f) / 256.0f * 2.0f - 1.0f;
    const float cx  = 0.5f * (tx0 + tx1);
    const float cy  = 0.5f * (ty0 + ty1);
    const float hx  = 0.5f * (tx1 - tx0);
    const float hy  = 0.5f * (ty1 - ty0);

    // subtile pixel-center rect (8x8)
    const float scx = ((float)(tileX * TILE + sbx) + 4.0f) / 128.0f - 1.0f;
    const float scy = ((float)(tileY * TILE + sby) + 4.0f) / 128.0f - 1.0f;
    const float shx = 3.5f / 128.0f;
    const float shy = 3.5f / 128.0f;
    const float dxs = scx - cx;
    const float dys = scy - cy;

    const float4* __restrict__ fa = g_fa + b * NF;
    const float4* __restrict__ fb = g_fb + b * NF;
    const float2* __restrict__ fc = g_fc + b * NF;
    const float4* __restrict__ bb = g_bb + b * NF;
    const float2* __restrict__ dd = g_dd + b * NF;

    float zmin0 = BIGF, zmin1 = BIGF;
    int   best0 = -1,   best1 = -1;
    float zmaxw = BIGF;   // warp-wide max of per-pixel zmin (refreshed periodically)

    const int fbeg = seg * SEGLEN;
    const int fend = min(fbeg + SEGLEN, NF);

    for (int base = fbeg; base < fend; base += CULL) {
        // ---- level 1: tile cull (coalesced, 1 face/thread) ----
        int f = base + tid;
        bool pass = false;
        float dc = 0.0f, beta = 0.0f, gamma = 0.0f;
        if (f < fend) {
            float4 bx = bb[f];
            pass = (bx.x <= tx1) & (bx.y >= tx0) & (bx.z <= ty1) & (bx.w >= ty0);
            if (pass) {
                float4 a  = fa[f];
                float4 c4 = fb[f];
                float z2  = fc[f].x;
                float dxc = cx - c4.x;
                float dyc = cy - c4.y;
                float w0c = a.x * dxc + a.y * dyc;
                float w1c = a.z * dxc + a.w * dyc;
                float w2c = 1.0f - w0c - w1c;
                float s0  = fabsf(a.x) * hx + fabsf(a.y) * hy;
                float s1  = fabsf(a.z) * hx + fabsf(a.w) * hy;
                float s2  = fabsf(a.x + a.z) * hx + fabsf(a.y + a.w) * hy;
                float m0  = 1e-5f * (fabsf(w0c) + s0) + 1e-6f;
                float m1  = 1e-5f * (fabsf(w1c) + s1) + 1e-6f;
                float m2  = 1e-5f * (fabsf(w2c) + s2) + 1e-6f;
                pass = (w0c + s0 >= -m0) & (w1c + s1 >= -m1) & (w2c + s2 >= -m2);
                if (pass) {
                    dc = w0c * c4.z + w1c * c4.w + w2c * z2;  // depth at tile center
                    float2 g = dd[f];
                    beta = g.x; gamma = g.y;
                }
            }
        }
        unsigned m = __ballot_sync(0xffffffffu, pass);
        if (lane == 0) s_wcnt[warp] = __popc(m);
        __syncthreads();

        int off = 0;
        int cnt = 0;
        #pragma unroll
        for (int w = 0; w < NWARPS; w++) {
            int c = s_wcnt[w];
            if (w < warp) off += c;
            cnt += c;
        }
        off += __popc(m & ((1u << lane) - 1u));
        if (pass) {
            s_fa[off] = fa[f];
            s_fb[off] = fb[f];
            s_fc[off] = fc[f];
            s_dd[off] = make_float4(dc, beta, gamma, 0.0f);
        }
        __syncthreads();

        // ---- level 2: per-warp 8x8 subtile cull + conservative min-depth ----
        int scnt = 0;
        for (int j0 = 0; j0 < cnt; j0 += 32) {
            int j = j0 + lane;
            bool sp = false;
            float dmins = 0.0f;
            if (j < cnt) {
                float4 a  = s_fa[j];
                float2 xy = make_float2(s_fb[j].x, s_fb[j].y);
                float dxc = scx - xy.x;
                float dyc = scy - xy.y;
                float w0c = a.x * dxc + a.y * dyc;
                float w1c = a.z * dxc + a.w * dyc;
                float w2c = 1.0f - w0c - w1c;
                float s0  = fabsf(a.x) * shx + fabsf(a.y) * shy;
                float s1  = fabsf(a.z) * shx + fabsf(a.w) * shy;
                float s2  = fabsf(a.x + a.z) * shx + fabsf(a.y + a.w) * shy;
                float m0  = 1e-5f * (fabsf(w0c) + s0) + 1e-6f;
                float m1  = 1e-5f * (fabsf(w1c) + s1) + 1e-6f;
                float m2  = 1e-5f * (fabsf(w2c) + s2) + 1e-6f;
                sp = (w0c + s0 >= -m0) & (w1c + s1 >= -m1) & (w2c + s2 >= -m2);
                if (sp) {
                    float4 dv = s_dd[j];
                    float sd  = fabsf(dv.y) * shx + fabsf(dv.z) * shy;
                    float dcs = dv.x + dv.y * dxs + dv.z * dys;   // depth at subtile center
                    float mg  = 1e-4f * (fabsf(dcs) + sd) + 1e-5f;
                    dmins = dcs - sd - mg;
                    // early-z at compaction time (exact: behind faces can't win)
                    sp = dmins <= zmaxw;
                }
            }
            unsigned sm = __ballot_sync(0xffffffffu, sp);
            if (sp) s_sub[warp][scnt + __popc(sm & ((1u << lane) - 1u))] =
                        make_float2(dmins, __int_as_float(j));
            scnt += __popc(sm);
        }

        // ---- sweep: this warp's subtile list, 2px/lane, early-z skip ----
        for (int k = 0; k < scnt; k++) {
            if ((k & 15) == 0) {
                float zm = fmaxf(zmin0, zmin1);
                #pragma unroll
                for (int d = 16; d >= 1; d >>= 1)
                    zm = fmaxf(zm, __shfl_xor_sync(0xffffffffu, zm, d));
                zmaxw = zm;
            }
            float2 di = s_sub[warp][k];
            if (di.x > zmaxw) continue;          // uniform skip: face behind all pixels
            int idx   = __float_as_int(di.y);
            float4 a  = s_fa[idx];
            float4 c4 = s_fb[idx];
            float2 e  = s_fc[idx];
            float dy  = py  - c4.y;
            float dx0 = px0 - c4.x;
            float dx1 = px1 - c4.x;
            float t0  = a.y * dy;
            float t1  = a.w * dy;
            float w0a = fmaf(a.x, dx0, t0);
            float w0b = fmaf(a.x, dx1, t0);
            float w1a = fmaf(a.z, dx0, t1);
            float w1b = fmaf(a.z, dx1, t1);
            float w2a = 1.0f - w0a - w1a;
            float w2b = 1.0f - w0b - w1b;
            float da  = fmaf(w0a, c4.z, fmaf(w1a, c4.w, w2a * e.x));
            float db  = fmaf(w0b, c4.z, fmaf(w1b, c4.w, w2b * e.x));
            int oa = __float_as_int(w0a) | __float_as_int(w1a) | __float_as_int(w2a);
            int ob = __float_as_int(w0b) | __float_as_int(w1b) | __float_as_int(w2b);
            if ((oa >= 0) && (da < zmin0)) { zmin0 = da; best0 = __float_as_int(e.y); }
            if ((ob >= 0) && (db < zmin1)) { zmin1 = db; best1 = __float_as_int(e.y); }
        }
        __syncthreads();
    }

    unsigned long long* zb = g_zb + (size_t)b * PP;
    if (best0 >= 0) {
        unsigned long long key =
            ((unsigned long long)f2sortable(zmin0) << 32) | (unsigned int)best0;
        atomicMin(&zb[py_i * WW + px0_i], key);
    }
    if (best1 >= 0) {
        unsigned long long key =
            ((unsigned long long)f2sortable(zmin1) << 32) | (unsigned int)best1;
        atomicMin(&zb[py_i * WW + px0_i + 1], key);
    }
}

__global__ __launch_bounds__(256) void resolve_kernel(const float* __restrict__ src_img,
                                                      float* __restrict__ out)
{
    const int b   = blockIdx.y;
    const int pix = blockIdx.x * 256 + threadIdx.x;
    const int px_i = pix & (WW - 1);
    const int py_i = pix >> 8;
    const float px = ((float)px_i + 0.5f) / 256.0f * 2.0f - 1.0f;
    const float py = ((float)py_i + 0.5f) / 256.0f * 2.0f - 1.0f;

    unsigned long long key = g_zb[(size_t)b * PP + pix];
    unsigned int face = (unsigned int)(key & 0xFFFFFFFFull);

    float fx, fy;
    if (face != 0xFFFFFFFFu) {
        int gi = b * NF + (int)face;
        float4 a  = g_fa[gi];
        float4 c4 = g_fb[gi];
        float dx = px - c4.x;
        float dy = py - c4.y;
        float w0 = fmaf(a.x, dx, a.y * dy);
        float w1 = fmaf(a.z, dx, a.w * dy);
        float w2 = 1.0f - w0 - w1;
        float2 s0 = g_sf[gi * 3 + 0];
        float2 s1 = g_sf[gi * 3 + 1];
        float2 s2 = g_sf[gi * 3 + 2];
        fx = w0 * s0.x + w1 * s1.x + w2 * s2.x;
        fy = w0 * s0.y + w1 * s1.y + w2 * s2.y;
    } else {
        fx = -2.0f;
        fy = -2.0f;
    }

    float ix = fminf(fmaxf(((fx + 1.0f) * 256.0f - 1.0f) * 0.5f, 0.0f), 255.0f);
    float iy = fminf(fmaxf(((fy + 1.0f) * 256.0f - 1.0f) * 0.5f, 0.0f), 255.0f);
    float x0f = floorf(ix);
    float y0f = floorf(iy);
    float wx = ix - x0f;
    float wy = iy - y0f;
    int x0i = (int)x0f;
    int y0i = (int)y0f;
    int x1i = min(x0i + 1, WW - 1);
    int y1i = min(y0i + 1, HH - 1);

    float wa = (1.0f - wx) * (1.0f - wy);
    float wb = wx * (1.0f - wy);
    float wc = (1.0f - wx) * wy;
    float wd = wx * wy;

    const float* img = src_img + (size_t)b * 3 * HH * WW;
    #pragma unroll
    for (int c = 0; c < 3; c++) {
        const float* p = img + (size_t)c * HH * WW;
        float Ia = p[y0i * WW + x0i];
        float Ib = p[y0i * WW + x1i];
        float Ic = p[y1i * WW + x0i];
        float Id = p[y1i * WW + x1i];
        out[(((size_t)b * 3 + c) * HH + py_i) * WW + px_i] =
            Ia * wa + Ib * wb + Ic * wc + Id * wd;
    }
}

extern "C" void kernel_launch(void* const* d_in, const int* in_sizes, int n_in,
                              void* d_out, int out_size)
{
    const float* src_img   = (const float*)d_in[0];
    const float* src_cam   = (const float*)d_in[1];
    const float* src_verts = (const float*)d_in[2];
    const float* tgt_cam   = (const float*)d_in[3];
    const float* tgt_verts = (const float*)d_in[4];
    const int*   faces     = (const int*)d_in[5];
    float* out = (float*)d_out;

    int n = BATCH * NF;
    setup_kernel<<<(n + 255) / 256, 256>>>(src_cam, src_verts, tgt_cam, tgt_verts, faces);
    zinit_kernel<<<(BATCH * PP + 255) / 256, 256>>>();
    dim3 rgrid(256, NSEG, BATCH);
    raster_kernel<<<rgrid, CULL>>>();
    dim3 ggrid(PP / 256, BATCH);
    resolve_kernel<<<ggrid, 256>>>(src_img, out);
}